// round 9
// baseline (speedup 1.0000x reference)
#include <cuda_runtime.h>

// RotaryEmbedding: x (4,16,8192,64) fp32. Rotate first 4 pairs (elems 0..7)
// of each 64-float row; copy the remaining 56 floats unchanged.
//
// Evidence log:
//  R3 plain LDG/STG CHUNKS=8 TPB=256: hot 35.3us, DRAM 75.9% <- best
//  R4 ldcs+stcs: 37.3 | R6 stcs only: 37.9  -> stcs ~ +2.6us (evict-first
//     writes force DRAM writeback; default WB lets dirty output lines be
//     overwritten in L2 next replay without ever draining)
//  R5 reg cap: spills, never cap | R7 CHUNKS=16: occ*MLP invariant (RF-bound)
//  R8 TMA bulk staging: 35.36us, DRAM 75.5% -> identical to R3. Request
//     supply is NOT the limiter; ~6.0 TB/s is the system ceiling for this mix.
//
// R9: complete the hint matrix with the one untested cell: __ldcs loads
// (stream the read-once input, stop it displacing retained write lines),
// DEFAULT stores (preserve cross-replay dirty-line retention).

#define CHUNKS 8
#define TPB 256

__device__ __forceinline__ void rope_math(float4 v[CHUNKS], int col4,
                                          const float* __restrict__ dparam,
                                          const float* __restrict__ thetas)
{
    if (col4 < 2) {
        // direction = sigmoid(d)*2 - 1 = tanh(d/2)
        float d = tanhf(0.5f * dparam[0]);
        int p = col4 * 2;
        float s0, c0, s1, c1;
        sincosf(d * thetas[p],     &s0, &c0);
        sincosf(d * thetas[p + 1], &s1, &c1);
        #pragma unroll
        for (int k = 0; k < CHUNKS; k++) {
            float xi0 = v[k].x, xj0 = v[k].y;
            float xi1 = v[k].z, xj1 = v[k].w;
            v[k].x =  xi0 * c0 + xj0 * s0;
            v[k].y = -xi0 * s0 + xj0 * c0;
            v[k].z =  xi1 * c1 + xj1 * s1;
            v[k].w = -xi1 * s1 + xj1 * c1;
        }
    }
}

// Fast path: grid covers n4 exactly, no guards.
__global__ __launch_bounds__(TPB) void rope8_exact(
    const float4* __restrict__ x,
    const float*  __restrict__ dparam,
    const float*  __restrict__ thetas,
    float4*       __restrict__ out)
{
    int base = blockIdx.x * (TPB * CHUNKS) + threadIdx.x;

    float4 v[CHUNKS];
    #pragma unroll
    for (int k = 0; k < CHUNKS; k++)
        v[k] = __ldcs(&x[base + k * TPB]);   // evict-first READS only

    rope_math(v, base & 15, dparam, thetas);

    #pragma unroll
    for (int k = 0; k < CHUNKS; k++)
        out[base + k * TPB] = v[k];          // default write-back stores
}

// Guarded fallback (not taken for the bench shape).
__global__ __launch_bounds__(TPB) void rope8_guarded(
    const float4* __restrict__ x,
    const float*  __restrict__ dparam,
    const float*  __restrict__ thetas,
    float4*       __restrict__ out,
    int n4)
{
    int base = blockIdx.x * (TPB * CHUNKS) + threadIdx.x;

    float4 v[CHUNKS];
    #pragma unroll
    for (int k = 0; k < CHUNKS; k++) {
        int i = base + k * TPB;
        if (i < n4) v[k] = __ldcs(&x[i]);
    }

    rope_math(v, base & 15, dparam, thetas);

    #pragma unroll
    for (int k = 0; k < CHUNKS; k++) {
        int i = base + k * TPB;
        if (i < n4) out[i] = v[k];
    }
}

extern "C" void kernel_launch(void* const* d_in, const int* in_sizes, int n_in,
                              void* d_out, int out_size)
{
    const float4* x      = (const float4*)d_in[0];
    const float*  dparam = (const float*)d_in[1];
    const float*  thetas = (const float*)d_in[2];
    float4*       out    = (float4*)d_out;

    int n4 = in_sizes[0] / 4;                   // 8,388,608 float4 chunks
    const int per_block = TPB * CHUNKS;         // 2048
    if (n4 % per_block == 0) {
        rope8_exact<<<n4 / per_block, TPB>>>(x, dparam, thetas, out);
    } else {
        int blocks = (n4 + per_block - 1) / per_block;
        rope8_guarded<<<blocks, TPB>>>(x, dparam, thetas, out, n4);
    }
}